// round 16
// baseline (speedup 1.0000x reference)
#include <cuda_runtime.h>
#include <cuda_fp16.h>
#include <cstdint>

#define S_TOK 4096
#define C_DIM 512
#define D_DIM 512
#define BATCH 4
#define NQKV  1536

// ---------------------------------------------------------------------------
// Scratch (device globals; no allocations allowed)
// ---------------------------------------------------------------------------
__device__ __half g_xh[(size_t)BATCH * S_TOK * C_DIM];
__device__ __half g_Wqkv[NQKV * C_DIM];                  // rows: Wq | Wk | Wvo
__device__ float  g_bqkv[NQKV];                          // bq | bk | bvo
__device__ __half g_QKV[(size_t)BATCH * S_TOK * NQKV];   // cols: Q(scaled) | K
__device__ __half g_Vt[(size_t)BATCH * C_DIM * S_TOK];   // (x·Wvo^T+bvo)^T c-major
__device__ __half g_P [(size_t)BATCH * S_TOK * S_TOK];   // exp(logits), fp16
__device__ float  g_Sums[(size_t)BATCH * S_TOK];         // softmax row sums

// ---------------------------------------------------------------------------
// PTX helpers (sm_103-portable: mma.sync / ldmatrix / cp.async only)
// ---------------------------------------------------------------------------
__device__ __forceinline__ uint32_t smem_u32(const void* p) {
    uint32_t a;
    asm("{ .reg .u64 t; cvta.to.shared.u64 t, %1; cvt.u32.u64 %0, t; }"
        : "=r"(a) : "l"(p));
    return a;
}

#define CP16(dst, src) \
    asm volatile("cp.async.cg.shared.global [%0], [%1], 16;" \
                 :: "r"(dst), "l"(src) : "memory")
#define CP_COMMIT() asm volatile("cp.async.commit_group;" ::: "memory")
#define CP_WAIT(n)  asm volatile("cp.async.wait_group %0;" :: "n"(n) : "memory")

#define LDSM_X4(r, addr)                                                      \
    asm volatile("ldmatrix.sync.aligned.m8n8.x4.shared.b16 {%0,%1,%2,%3}, [%4];" \
                 : "=r"((r)[0]), "=r"((r)[1]), "=r"((r)[2]), "=r"((r)[3])     \
                 : "r"(addr))

#define MMA16816(d, a, b0, b1)                                                \
    asm volatile("mma.sync.aligned.m16n8k16.row.col.f32.f16.f16.f32 "        \
                 "{%0,%1,%2,%3}, {%4,%5,%6,%7}, {%8,%9}, {%0,%1,%2,%3};"     \
                 : "+f"((d)[0]), "+f"((d)[1]), "+f"((d)[2]), "+f"((d)[3])    \
                 : "r"((a)[0]), "r"((a)[1]), "r"((a)[2]), "r"((a)[3]),       \
                   "r"(b0), "r"(b1))

// One full 64x32x16 warp pass: 4 mi x 4 n8 MMAs (fp32 acc)
#define MMA_PASS(af, bf)                                                      \
    _Pragma("unroll")                                                         \
    for (int mi = 0; mi < 4; mi++) {                                          \
        _Pragma("unroll")                                                     \
        for (int ng = 0; ng < 2; ng++) {                                      \
            MMA16816(acc[mi][2 * ng],     (af)[mi], (bf)[ng][0], (bf)[ng][1]); \
            MMA16816(acc[mi][2 * ng + 1], (af)[mi], (bf)[ng][2], (bf)[ng][3]); \
        }                                                                     \
    }

// ---------------------------------------------------------------------------
// fp16 mma.sync GEMM (fp32 accumulators): acc(M,N) = sum_k A(m,k)*B(n,k).
// A,B k-contiguous with leading dims lda/ldb. Single pass.
// OUTMODE 0: FINAL, swapped orientation: M=C (rows of Vt), N=S (rows of P).
//            acc(c,s) = yraw[s,c]; store row-major fp32
//            out[c*ldc + s] = acc * inv(Sums[s]) + bias[c]      (coalesced)
//         1: fp16 row store of exp(acc); atomicAdd row sums->Cf (sim)
//         3: QKV dispatch: n<1024 row fp16 (acc+bias)*(n<512?scale:1),
//            n>=1024 transposed fp16 to Ch2 ((xWvo+bvo)^T)      (QKV proj)
// CTA 128(M) x 128(N), 8 warps of 64x32; K chunk 32 (80-byte padded rows,
// conflict-free); 4-stage cp.async, prefetch issued BEFORE compute;
// 1 barrier/chunk; 2 CTAs/SM.
// ---------------------------------------------------------------------------
template<int OUTMODE>
__global__ __launch_bounds__(256, 2)
void gemm(const __half* __restrict__ Ah, int lda, long aStride, int Ktot,
          const __half* __restrict__ Bh, int ldb, long bStride,
          float* __restrict__ Cf, __half* __restrict__ Ch,
          __half* __restrict__ Ch2, long cStride, long c2Stride, int ldc,
          const float* __restrict__ bias, const float* __restrict__ rowscale,
          float scale)
{
    constexpr int AH_OFF = 0;
    constexpr int BH_OFF = 10240;                       // A tile = 128*80
    constexpr int STAGE  = 20480;
    constexpr int NSTAGE = 4;

    extern __shared__ char smch[];
    const uint32_t sbase = smem_u32(smch);

    const int tid  = threadIdx.x;
    const int lane = tid & 31;
    const int wid  = tid >> 5;
    const int m0 = blockIdx.x * 128;
    const int n0 = blockIdx.y * 128;
    const int bz = blockIdx.z;

    const __half* ArowH = Ah + (long)bz * aStride + (long)m0 * lda;
    const __half* BrowH = Bh + (long)bz * bStride + (long)n0 * ldb;

    const int ldrow = tid >> 2;     // 0..63
    const int ldq   = tid & 3;      // 16B quarter of 64B row
    auto stage_load = [&](int c, int buf) {
        const long kof = (long)c << 5;
        const uint32_t s0 = sbase + buf * STAGE;
        #pragma unroll
        for (int i = 0; i < 2; i++) {                 // A: 128 rows
            const int row = ldrow + i * 64;
            const uint32_t doff = (uint32_t)(row * 80 + ldq * 16);
            const long goff = (long)row * lda + kof + ldq * 8;
            CP16(s0 + AH_OFF + doff, ArowH + goff);
        }
        #pragma unroll
        for (int i = 0; i < 2; i++) {                 // B: 128 rows
            const int row = ldrow + i * 64;
            const uint32_t doff = (uint32_t)(row * 80 + ldq * 16);
            const long goff = (long)row * ldb + kof + ldq * 8;
            CP16(s0 + BH_OFF + doff, BrowH + goff);
        }
    };

    float acc[4][4][4];
    #pragma unroll
    for (int i = 0; i < 4; i++)
        #pragma unroll
        for (int j = 0; j < 4; j++)
            #pragma unroll
            for (int q = 0; q < 4; q++) acc[i][j][q] = 0.f;

    const int wr = wid & 1;         // 2 warps along M (64 each)
    const int wc = wid >> 1;        // 4 warps along N (32 each)

    const uint32_t aAddr0 = (uint32_t)((wr * 64 + (lane & 15)) * 80 + ((lane >> 4) << 4));
    const uint32_t bAddr0 = (uint32_t)((wc * 32 + ((lane >> 4) << 3) + (lane & 7)) * 80
                                       + (((lane >> 3) & 1) << 4));

    const int nCh = Ktot >> 5;

    // prologue: fill NSTAGE-1 stages (one commit each)
    #pragma unroll
    for (int s = 0; s < NSTAGE - 1; s++) {
        if (s < nCh) stage_load(s, s);
        CP_COMMIT();
    }

    int bufc = 0;
    for (int c = 0; c < nCh; c++) {
        if (c + 2 < nCh)      { CP_WAIT(2); }
        else if (c + 1 < nCh) { CP_WAIT(1); }
        else                  { CP_WAIT(0); }
        __syncthreads();            // chunk c visible; buffer (c-1)%4 free

        // prefetch chunk c+3 into the buffer freed by chunk c-1 (pre-compute)
        if (c + NSTAGE - 1 < nCh) {
            int b2 = bufc + NSTAGE - 1; if (b2 >= NSTAGE) b2 -= NSTAGE;
            stage_load(c + NSTAGE - 1, b2);
        }
        CP_COMMIT();

        const uint32_t s0 = sbase + bufc * STAGE;
        #pragma unroll
        for (int k16 = 0; k16 < 2; k16++) {
            const uint32_t aA = s0 + AH_OFF + aAddr0 + k16 * 32;
            const uint32_t bA = s0 + BH_OFF + bAddr0 + k16 * 32;

            uint32_t ah[4][4], bb[2][4];
            #pragma unroll
            for (int mi = 0; mi < 4; mi++) LDSM_X4(ah[mi], aA + mi * 1280);
            #pragma unroll
            for (int ng = 0; ng < 2; ng++) LDSM_X4(bb[ng], bA + ng * 1280);

            MMA_PASS(ah, bb);
        }
        if (++bufc == NSTAGE) bufc = 0;
    }

    // ---- epilogue ----
    const int tq = lane >> 2;
    const int tr = lane & 3;

    if (OUTMODE == 0) {
        // swapped orientation: rows = channels, cols = tokens
        float invc[4][2];
        #pragma unroll
        for (int n8 = 0; n8 < 4; n8++) {
            const int cc = n0 + wc * 32 + n8 * 8 + tr * 2;
            invc[n8][0] = __fdividef(1.f, rowscale[(long)bz * S_TOK + cc]);
            invc[n8][1] = __fdividef(1.f, rowscale[(long)bz * S_TOK + cc + 1]);
        }
        #pragma unroll
        for (int mi = 0; mi < 4; mi++) {
            const int r = m0 + wr * 64 + mi * 16 + tq;   // channel
            const float b0 = bias[r], b1 = bias[r + 8];
            float* row0 = Cf + (long)bz * cStride + (long)r * ldc;
            float* row1 = row0 + (long)8 * ldc;
            #pragma unroll
            for (int n8 = 0; n8 < 4; n8++) {
                const int cc = n0 + wc * 32 + n8 * 8 + tr * 2;
                *reinterpret_cast<float2*>(row0 + cc) =
                    make_float2(acc[mi][n8][0] * invc[n8][0] + b0,
                                acc[mi][n8][1] * invc[n8][1] + b0);
                *reinterpret_cast<float2*>(row1 + cc) =
                    make_float2(acc[mi][n8][2] * invc[n8][0] + b1,
                                acc[mi][n8][3] * invc[n8][1] + b1);
            }
        }
        return;
    }

    #pragma unroll
    for (int mi = 0; mi < 4; mi++) {
        const int r = m0 + wr * 64 + mi * 16 + tq;
        float rs0 = 0.f, rs1 = 0.f;                   // OUTMODE==1 partial sums
        #pragma unroll
        for (int n8 = 0; n8 < 4; n8++) {
            const int cc = n0 + wc * 32 + n8 * 8 + tr * 2;

            if (OUTMODE == 1) {            // exp, fp16 row, accumulate sums
                const float e0 = __expf(acc[mi][n8][0]);
                const float e1 = __expf(acc[mi][n8][1]);
                const float e2 = __expf(acc[mi][n8][2]);
                const float e3 = __expf(acc[mi][n8][3]);
                rs0 += e0 + e1;  rs1 += e2 + e3;
                __half* base = Ch + (long)bz * cStride;
                *reinterpret_cast<__half2*>(base + (long)r * ldc + cc) =
                    __floats2half2_rn(e0, e1);
                *reinterpret_cast<__half2*>(base + (long)(r + 8) * ldc + cc) =
                    __floats2half2_rn(e2, e3);
            } else {                       // OUTMODE 3: QKV dispatch
                const float b0 = bias[cc], b1 = bias[cc + 1];
                const float sc = (n0 < 512) ? scale : 1.f;
                const float v00 = (acc[mi][n8][0] + b0) * sc;
                const float v01 = (acc[mi][n8][1] + b1) * sc;
                const float v10 = (acc[mi][n8][2] + b0) * sc;
                const float v11 = (acc[mi][n8][3] + b1) * sc;
                if (n0 < 1024) {           // Q | K: row-major into QKV
                    __half* base = Ch + (long)bz * cStride;
                    *reinterpret_cast<__half2*>(base + (long)r * ldc + cc) =
                        __floats2half2_rn(v00, v01);
                    *reinterpret_cast<__half2*>(base + (long)(r + 8) * ldc + cc) =
                        __floats2half2_rn(v10, v11);
                } else {                   // xWvo+bvo: transposed into Vt
                    __half* base = Ch2 + (long)bz * c2Stride;
                    const int d = cc - 1024;
                    base[(long)d * S_TOK + r]           = __float2half_rn(v00);
                    base[(long)(d + 1) * S_TOK + r]     = __float2half_rn(v01);
                    base[(long)d * S_TOK + r + 8]       = __float2half_rn(v10);
                    base[(long)(d + 1) * S_TOK + r + 8] = __float2half_rn(v11);
                }
            }
        }
        if (OUTMODE == 1) {
            rs0 += __shfl_xor_sync(0xffffffffu, rs0, 1);
            rs0 += __shfl_xor_sync(0xffffffffu, rs0, 2);
            rs1 += __shfl_xor_sync(0xffffffffu, rs1, 1);
            rs1 += __shfl_xor_sync(0xffffffffu, rs1, 2);
            if (tr == 0) {
                atomicAdd(Cf + (long)bz * S_TOK + r,     rs0);
                atomicAdd(Cf + (long)bz * S_TOK + r + 8, rs1);
            }
        }
    }
}

// ---------------------------------------------------------------------------
// Prep: transpose x (B,C,S) fp32 -> xh (B,S,C) fp16
// ---------------------------------------------------------------------------
__global__ __launch_bounds__(256)
void transpose_x(const float* __restrict__ x, __half* __restrict__ xh)
{
    __shared__ float t[32][33];
    const int b = blockIdx.z;
    const int s0 = blockIdx.x << 5, c0 = blockIdx.y << 5;
    const float* xb = x + (long)b * C_DIM * S_TOK;
    const int a = threadIdx.x & 31, q8 = threadIdx.x >> 5;
    #pragma unroll
    for (int i = 0; i < 4; i++) {
        int cc = q8 + (i << 3);
        t[cc][a] = xb[(long)(c0 + cc) * S_TOK + s0 + a];
    }
    __syncthreads();
    const long ob = (long)b * S_TOK * C_DIM;
    #pragma unroll
    for (int i = 0; i < 4; i++) {
        int ss = q8 + (i << 3);
        xh[ob + (long)(s0 + ss) * C_DIM + c0 + a] = __float2half_rn(t[a][ss]);
    }
}

// Wq/Wk fp16 conversion; bq/bk copy; bvo = Wo·bv; zero softmax row sums
__global__ __launch_bounds__(256)
void prep_w(const float* __restrict__ Wq, const float* __restrict__ Wk,
            const float* __restrict__ Wo, const float* __restrict__ bq,
            const float* __restrict__ bk, const float* __restrict__ bv,
            __half* __restrict__ Wqkv, float* __restrict__ bqkv,
            float* __restrict__ sums)
{
    const int NW = D_DIM * C_DIM;
    int i = blockIdx.x * 256 + threadIdx.x;
    if (i < NW) {
        Wqkv[i]      = __float2half_rn(Wq[i]);
        Wqkv[i + NW] = __float2half_rn(Wk[i]);
    }
    if (i < 512)              bqkv[i] = bq[i];
    else if (i < 1024)        bqkv[i] = bk[i - 512];
    else if (i < 1536) {      // bvo[c] = sum_d bv[d] * Wo[c,d]
        const float* worow = Wo + (long)(i - 1024) * D_DIM;
        float s = 0.f;
        #pragma unroll 8
        for (int d = 0; d < D_DIM; d++) s += bv[d] * worow[d];
        bqkv[i] = s;
    }
    if (i < BATCH * S_TOK)    sums[i] = 0.f;
}

// Wvo[c][c'] = sum_d Wo[c,d] * Wv[d,c']  -> fp16 into Wqkv rows 1024..1535
__global__ __launch_bounds__(256)
void prep_wvo(const float* __restrict__ Wo, const float* __restrict__ Wv,
              __half* __restrict__ Wqkv)
{
    __shared__ float to[32][33], tv[32][33];
    const int c0  = blockIdx.y << 5;
    const int c20 = blockIdx.x << 5;
    const int tx = threadIdx.x & 31, ty = threadIdx.x >> 5;   // 32 x 8

    float acc[4] = {0.f, 0.f, 0.f, 0.f};
    for (int kt = 0; kt < C_DIM; kt += 32) {
        #pragma unroll
        for (int i = 0; i < 4; i++)
            to[ty + (i << 3)][tx] = Wo[(long)(c0 + ty + (i << 3)) * D_DIM + kt + tx];
        #pragma unroll
        for (int i = 0; i < 4; i++)
            tv[ty + (i << 3)][tx] = Wv[(long)(kt + ty + (i << 3)) * C_DIM + c20 + tx];
        __syncthreads();
        #pragma unroll
        for (int kk = 0; kk < 32; kk++) {
            const float v = tv[kk][tx];
            #pragma unroll
            for (int q = 0; q < 4; q++)
                acc[q] += to[(ty << 2) + q][kk] * v;
        }
        __syncthreads();
    }
    #pragma unroll
    for (int q = 0; q < 4; q++)
        Wqkv[(long)(1024 + c0 + (ty << 2) + q) * C_DIM + c20 + tx] =
            __float2half_rn(acc[q]);
}

// ---------------------------------------------------------------------------
extern "C" void kernel_launch(void* const* d_in, const int* in_sizes, int n_in,
                              void* d_out, int out_size)
{
    const float* x  = (const float*)d_in[0];
    const float* Wq = (const float*)d_in[1];
    const float* bq = (const float*)d_in[2];
    const float* Wk = (const float*)d_in[3];
    const float* bk = (const float*)d_in[4];
    const float* Wv = (const float*)d_in[5];
    const float* bv = (const float*)d_in[6];
    const float* Wo = (const float*)d_in[7];
    const float* bo = (const float*)d_in[8];
    float* out = (float*)d_out;

    __half *xh, *Wqkv, *QKV, *Vt, *P;
    float *bqkv, *Sums;
    cudaGetSymbolAddress((void**)&xh, g_xh);
    cudaGetSymbolAddress((void**)&Wqkv, g_Wqkv);
    cudaGetSymbolAddress((void**)&bqkv, g_bqkv);
    cudaGetSymbolAddress((void**)&QKV, g_QKV);
    cudaGetSymbolAddress((void**)&Vt, g_Vt);
    cudaGetSymbolAddress((void**)&P, g_P);
    cudaGetSymbolAddress((void**)&Sums, g_Sums);

    const int S1 = 4 * 20480;      // 4-stage, 80 KB/CTA (2 CTAs/SM)
    cudaFuncSetAttribute(gemm<3>, cudaFuncAttributeMaxDynamicSharedMemorySize, S1);
    cudaFuncSetAttribute(gemm<1>, cudaFuncAttributeMaxDynamicSharedMemorySize, S1);
    cudaFuncSetAttribute(gemm<0>, cudaFuncAttributeMaxDynamicSharedMemorySize, S1);

    const long SS  = (long)S_TOK * S_TOK;
    const long SC  = (long)S_TOK * C_DIM;
    const long SQ  = (long)S_TOK * NQKV;
    const long CS  = (long)C_DIM * S_TOK;
    const float attn_scale = 0.044194173824159216f;   // 512^-0.5

    // ---- prep ----
    transpose_x<<<dim3(S_TOK / 32, C_DIM / 32, BATCH), 256>>>(x, xh);
    prep_w<<<(D_DIM * C_DIM + 255) / 256, 256>>>(Wq, Wk, Wo, bq, bk, bv,
                                                 Wqkv, bqkv, Sums);
    prep_wvo<<<dim3(16, 16), 256>>>(Wo, Wv, Wqkv);

    // ---- fused projection: Q(scaled) | K row-major; xWvo+bvo transposed ----
    gemm<3><<<dim3(32, 12, BATCH), 256, S1>>>(
        xh, C_DIM, SC, C_DIM, Wqkv, C_DIM, 0,
        nullptr, QKV, Vt, SQ, SC, NQKV, bqkv, nullptr, attn_scale);

    // ---- P = exp(Q K^T) (fp32 acc); row sums -> Sums ----
    gemm<1><<<dim3(32, 32, BATCH), 256, S1>>>(
        QKV, NQKV, SQ, D_DIM, QKV + 512, NQKV, SQ,
        Sums, P, nullptr, SS, 0, S_TOK, nullptr, nullptr, 1.f);

    // ---- y^T: acc(c,s) = sum_t VWo[t,c]·P[s,t]; store (B,C,S) coalesced ----
    gemm<0><<<dim3(4, 32, BATCH), 256, S1>>>(
        Vt, S_TOK, SC, S_TOK, P, S_TOK, SS,
        out, nullptr, nullptr, CS, 0, S_TOK, bo, Sums, 1.f);
}

// round 17
// speedup vs baseline: 1.1765x; 1.1765x over previous
#include <cuda_runtime.h>
#include <cuda_fp16.h>
#include <cstdint>

#define S_TOK 4096
#define C_DIM 512
#define D_DIM 512
#define BATCH 4
#define NQKV  1536
#define NQK   1024

// ---------------------------------------------------------------------------
// Scratch (device globals; no allocations allowed)
// ---------------------------------------------------------------------------
__device__ __half g_xh[(size_t)BATCH * S_TOK * C_DIM];
__device__ __half g_Wqkv[NQKV * C_DIM];                  // rows: Wq | Wk | Wv
__device__ float  g_bqkv[NQKV];
__device__ __half g_Wo[C_DIM * D_DIM];
__device__ __half g_QK[(size_t)BATCH * S_TOK * NQK];     // cols: Q(scaled) | K
__device__ __half g_Vt[(size_t)BATCH * D_DIM * S_TOK];   // V^T (d-major)
__device__ __half g_P [(size_t)BATCH * S_TOK * S_TOK];   // exp(logits), fp16
__device__ float  g_Sums[(size_t)BATCH * S_TOK];         // softmax row sums
__device__ __half g_O [(size_t)BATCH * S_TOK * D_DIM];

// ---------------------------------------------------------------------------
// PTX helpers (sm_103-portable: mma.sync / ldmatrix / cp.async only)
// ---------------------------------------------------------------------------
__device__ __forceinline__ uint32_t smem_u32(const void* p) {
    uint32_t a;
    asm("{ .reg .u64 t; cvta.to.shared.u64 t, %1; cvt.u32.u64 %0, t; }"
        : "=r"(a) : "l"(p));
    return a;
}

#define CP16(dst, src) \
    asm volatile("cp.async.cg.shared.global [%0], [%1], 16;" \
                 :: "r"(dst), "l"(src) : "memory")
#define CP_COMMIT() asm volatile("cp.async.commit_group;" ::: "memory")
#define CP_WAIT(n)  asm volatile("cp.async.wait_group %0;" :: "n"(n) : "memory")

#define LDSM_X4(r, addr)                                                      \
    asm volatile("ldmatrix.sync.aligned.m8n8.x4.shared.b16 {%0,%1,%2,%3}, [%4];" \
                 : "=r"((r)[0]), "=r"((r)[1]), "=r"((r)[2]), "=r"((r)[3])     \
                 : "r"(addr))

#define MMA16816(d, a, b0, b1)                                                \
    asm volatile("mma.sync.aligned.m16n8k16.row.col.f32.f16.f16.f32 "        \
                 "{%0,%1,%2,%3}, {%4,%5,%6,%7}, {%8,%9}, {%0,%1,%2,%3};"     \
                 : "+f"((d)[0]), "+f"((d)[1]), "+f"((d)[2]), "+f"((d)[3])    \
                 : "r"((a)[0]), "r"((a)[1]), "r"((a)[2]), "r"((a)[3]),       \
                   "r"(b0), "r"(b1))

// One full 64x32x16 warp pass: 4 mi x 4 n8 MMAs (fp32 acc)
#define MMA_PASS(af, bf)                                                      \
    _Pragma("unroll")                                                         \
    for (int mi = 0; mi < 4; mi++) {                                          \
        _Pragma("unroll")                                                     \
        for (int ng = 0; ng < 2; ng++) {                                      \
            MMA16816(acc[mi][2 * ng],     (af)[mi], (bf)[ng][0], (bf)[ng][1]); \
            MMA16816(acc[mi][2 * ng + 1], (af)[mi], (bf)[ng][2], (bf)[ng][3]); \
        }                                                                     \
    }

// ---------------------------------------------------------------------------
// fp16 mma.sync GEMM (fp32 accumulators): acc(M,N) = sum_k A(m,k)*B(n,k).
// A,B k-contiguous with leading dims lda/ldb. Single pass (Ah*Bh).
// OUTMODE 0: fp32 transposed store, (acc+bias)*scale            (out-proj)
//         1: fp16 row store of exp(acc); atomicAdd row sums->Cf (sim)
//         2: fp16 row store of acc / rowsum[row]                (PV)
//         3: QKV dispatch: n<1024 row fp16 (acc+bias)*(n<512?scale:1) -> Ch,
//            n>=1024 transposed fp16 to Ch2 (V^T)               (QKV proj)
// CTA 128(M) x 128(N), 8 warps of 64x32; K chunk 32 (80-byte padded rows,
// conflict-free); 4-stage cp.async; 1 barrier/chunk; 2 CTAs/SM.
// ---------------------------------------------------------------------------
template<int OUTMODE>
__global__ __launch_bounds__(256, 2)
void gemm(const __half* __restrict__ Ah, int lda, long aStride, int Ktot,
          const __half* __restrict__ Bh, int ldb, long bStride,
          float* __restrict__ Cf, __half* __restrict__ Ch,
          __half* __restrict__ Ch2, long cStride, long c2Stride, int ldc,
          const float* __restrict__ bias, const float* __restrict__ rowscale,
          float scale)
{
    constexpr int AH_OFF = 0;
    constexpr int BH_OFF = 10240;                       // A tile = 128*80
    constexpr int STAGE  = 20480;
    constexpr int NSTAGE = 4;

    extern __shared__ char smch[];
    const uint32_t sbase = smem_u32(smch);

    const int tid  = threadIdx.x;
    const int lane = tid & 31;
    const int wid  = tid >> 5;
    const int m0 = blockIdx.x * 128;
    const int n0 = blockIdx.y * 128;
    const int bz = blockIdx.z;

    const __half* ArowH = Ah + (long)bz * aStride + (long)m0 * lda;
    const __half* BrowH = Bh + (long)bz * bStride + (long)n0 * ldb;

    const int ldrow = tid >> 2;     // 0..63
    const int ldq   = tid & 3;      // 16B quarter of 64B row
    auto stage_load = [&](int c, int buf) {
        const long kof = (long)c << 5;
        const uint32_t s0 = sbase + buf * STAGE;
        #pragma unroll
        for (int i = 0; i < 2; i++) {                 // A: 128 rows
            const int row = ldrow + i * 64;
            const uint32_t doff = (uint32_t)(row * 80 + ldq * 16);
            const long goff = (long)row * lda + kof + ldq * 8;
            CP16(s0 + AH_OFF + doff, ArowH + goff);
        }
        #pragma unroll
        for (int i = 0; i < 2; i++) {                 // B: 128 rows
            const int row = ldrow + i * 64;
            const uint32_t doff = (uint32_t)(row * 80 + ldq * 16);
            const long goff = (long)row * ldb + kof + ldq * 8;
            CP16(s0 + BH_OFF + doff, BrowH + goff);
        }
    };

    float acc[4][4][4];
    #pragma unroll
    for (int i = 0; i < 4; i++)
        #pragma unroll
        for (int j = 0; j < 4; j++)
            #pragma unroll
            for (int q = 0; q < 4; q++) acc[i][j][q] = 0.f;

    const int wr = wid & 1;         // 2 warps along M (64 each)
    const int wc = wid >> 1;        // 4 warps along N (32 each)

    const uint32_t aAddr0 = (uint32_t)((wr * 64 + (lane & 15)) * 80 + ((lane >> 4) << 4));
    const uint32_t bAddr0 = (uint32_t)((wc * 32 + ((lane >> 4) << 3) + (lane & 7)) * 80
                                       + (((lane >> 3) & 1) << 4));

    const int nCh = Ktot >> 5;

    // prologue: fill NSTAGE-1 stages (one commit each)
    #pragma unroll
    for (int s = 0; s < NSTAGE - 1; s++) {
        if (s < nCh) stage_load(s, s);
        CP_COMMIT();
    }

    int bufc = 0;
    for (int c = 0; c < nCh; c++) {
        if (c + 2 < nCh)      { CP_WAIT(2); }
        else if (c + 1 < nCh) { CP_WAIT(1); }
        else                  { CP_WAIT(0); }
        __syncthreads();            // chunk c visible; oldest buffer free
        const uint32_t s0 = sbase + bufc * STAGE;
        #pragma unroll
        for (int k16 = 0; k16 < 2; k16++) {
            const uint32_t aA = s0 + AH_OFF + aAddr0 + k16 * 32;
            const uint32_t bA = s0 + BH_OFF + bAddr0 + k16 * 32;

            uint32_t ah[4][4], bb[2][4];
            #pragma unroll
            for (int mi = 0; mi < 4; mi++) LDSM_X4(ah[mi], aA + mi * 1280);
            #pragma unroll
            for (int ng = 0; ng < 2; ng++) LDSM_X4(bb[ng], bA + ng * 1280);

            MMA_PASS(ah, bb);
        }
        if (c + NSTAGE - 1 < nCh) {
            int b2 = bufc + NSTAGE - 1; if (b2 >= NSTAGE) b2 -= NSTAGE;
            stage_load(c + NSTAGE - 1, b2);
        }
        CP_COMMIT();
        if (++bufc == NSTAGE) bufc = 0;
    }

    // ---- epilogue ----
    const int tq = lane >> 2;
    const int tr = lane & 3;

    #pragma unroll
    for (int mi = 0; mi < 4; mi++) {
        const int r = m0 + wr * 64 + mi * 16 + tq;
        float inv0 = 1.f, inv1 = 1.f;
        if (OUTMODE == 2) {
            inv0 = __fdividef(1.f, rowscale[(long)bz * S_TOK + r]);
            inv1 = __fdividef(1.f, rowscale[(long)bz * S_TOK + r + 8]);
        }
        float rs0 = 0.f, rs1 = 0.f;                   // OUTMODE==1 partial sums
        #pragma unroll
        for (int n8 = 0; n8 < 4; n8++) {
            const int cc = n0 + wc * 32 + n8 * 8 + tr * 2;

            if (OUTMODE == 0) {            // fp32 transposed + bias
                const float b0 = bias[cc], b1 = bias[cc + 1];
                float* base = Cf + (long)bz * cStride;
                base[(long)cc * ldc + r]           = (acc[mi][n8][0] + b0) * scale;
                base[(long)(cc + 1) * ldc + r]     = (acc[mi][n8][1] + b1) * scale;
                base[(long)cc * ldc + r + 8]       = (acc[mi][n8][2] + b0) * scale;
                base[(long)(cc + 1) * ldc + r + 8] = (acc[mi][n8][3] + b1) * scale;
            } else if (OUTMODE == 1) {     // exp, fp16 row, accumulate sums
                const float e0 = __expf(acc[mi][n8][0]);
                const float e1 = __expf(acc[mi][n8][1]);
                const float e2 = __expf(acc[mi][n8][2]);
                const float e3 = __expf(acc[mi][n8][3]);
                rs0 += e0 + e1;  rs1 += e2 + e3;
                __half* base = Ch + (long)bz * cStride;
                *reinterpret_cast<__half2*>(base + (long)r * ldc + cc) =
                    __floats2half2_rn(e0, e1);
                *reinterpret_cast<__half2*>(base + (long)(r + 8) * ldc + cc) =
                    __floats2half2_rn(e2, e3);
            } else if (OUTMODE == 2) {     // row-scaled, fp16 row
                __half* base = Ch + (long)bz * cStride;
                *reinterpret_cast<__half2*>(base + (long)r * ldc + cc) =
                    __floats2half2_rn(acc[mi][n8][0] * inv0, acc[mi][n8][1] * inv0);
                *reinterpret_cast<__half2*>(base + (long)(r + 8) * ldc + cc) =
                    __floats2half2_rn(acc[mi][n8][2] * inv1, acc[mi][n8][3] * inv1);
            } else {                       // OUTMODE 3: QKV dispatch
                const float b0 = bias[cc], b1 = bias[cc + 1];
                const float sc = (n0 < 512) ? scale : 1.f;
                const float v00 = (acc[mi][n8][0] + b0) * sc;
                const float v01 = (acc[mi][n8][1] + b1) * sc;
                const float v10 = (acc[mi][n8][2] + b0) * sc;
                const float v11 = (acc[mi][n8][3] + b1) * sc;
                if (n0 < 1024) {           // Q | K: row-major into QK (ld 1024)
                    __half* base = Ch + (long)bz * cStride;
                    *reinterpret_cast<__half2*>(base + (long)r * ldc + cc) =
                        __floats2half2_rn(v00, v01);
                    *reinterpret_cast<__half2*>(base + (long)(r + 8) * ldc + cc) =
                        __floats2half2_rn(v10, v11);
                } else {                   // V: transposed into Vt
                    __half* base = Ch2 + (long)bz * c2Stride;
                    const int d = cc - 1024;
                    base[(long)d * S_TOK + r]           = __float2half_rn(v00);
                    base[(long)(d + 1) * S_TOK + r]     = __float2half_rn(v01);
                    base[(long)d * S_TOK + r + 8]       = __float2half_rn(v10);
                    base[(long)(d + 1) * S_TOK + r + 8] = __float2half_rn(v11);
                }
            }
        }
        if (OUTMODE == 1) {
            // reduce partial sums over the 4 lanes sharing a row (tr = 0..3)
            rs0 += __shfl_xor_sync(0xffffffffu, rs0, 1);
            rs0 += __shfl_xor_sync(0xffffffffu, rs0, 2);
            rs1 += __shfl_xor_sync(0xffffffffu, rs1, 1);
            rs1 += __shfl_xor_sync(0xffffffffu, rs1, 2);
            if (tr == 0) {
                atomicAdd(Cf + (long)bz * S_TOK + r,     rs0);
                atomicAdd(Cf + (long)bz * S_TOK + r + 8, rs1);
            }
        }
    }
}

// ---------------------------------------------------------------------------
// Prep: transpose x (B,C,S) fp32 -> xh (B,S,C) fp16
// ---------------------------------------------------------------------------
__global__ __launch_bounds__(256)
void transpose_x(const float* __restrict__ x, __half* __restrict__ xh)
{
    __shared__ float t[32][33];
    const int b = blockIdx.z;
    const int s0 = blockIdx.x << 5, c0 = blockIdx.y << 5;
    const float* xb = x + (long)b * C_DIM * S_TOK;
    const int a = threadIdx.x & 31, q8 = threadIdx.x >> 5;
    #pragma unroll
    for (int i = 0; i < 4; i++) {
        int cc = q8 + (i << 3);
        t[cc][a] = xb[(long)(c0 + cc) * S_TOK + s0 + a];
    }
    __syncthreads();
    const long ob = (long)b * S_TOK * C_DIM;
    #pragma unroll
    for (int i = 0; i < 4; i++) {
        int ss = q8 + (i << 3);
        xh[ob + (long)(s0 + ss) * C_DIM + c0 + a] = __float2half_rn(t[a][ss]);
    }
}

// Build concatenated QKV weights + bias; convert Wo; zero softmax row sums
__global__ __launch_bounds__(256)
void prep_w(const float* __restrict__ Wq, const float* __restrict__ Wk,
            const float* __restrict__ Wv, const float* __restrict__ Wo,
            const float* __restrict__ bq, const float* __restrict__ bk,
            const float* __restrict__ bv,
            __half* __restrict__ Wqkv, __half* __restrict__ Woh,
            float* __restrict__ bqkv, float* __restrict__ sums)
{
    const int NW = D_DIM * C_DIM;
    int i = blockIdx.x * 256 + threadIdx.x;
    if (i < NW) {
        Wqkv[i]          = __float2half_rn(Wq[i]);
        Wqkv[i + NW]     = __float2half_rn(Wk[i]);
        Wqkv[i + 2 * NW] = __float2half_rn(Wv[i]);
        Woh[i]           = __float2half_rn(Wo[i]);
    }
    if (i < 512)              bqkv[i] = bq[i];
    else if (i < 1024)        bqkv[i] = bk[i - 512];
    else if (i < 1536)        bqkv[i] = bv[i - 1024];
    if (i < BATCH * S_TOK)    sums[i] = 0.f;
}

// ---------------------------------------------------------------------------
extern "C" void kernel_launch(void* const* d_in, const int* in_sizes, int n_in,
                              void* d_out, int out_size)
{
    const float* x  = (const float*)d_in[0];
    const float* Wq = (const float*)d_in[1];
    const float* bq = (const float*)d_in[2];
    const float* Wk = (const float*)d_in[3];
    const float* bk = (const float*)d_in[4];
    const float* Wv = (const float*)d_in[5];
    const float* bv = (const float*)d_in[6];
    const float* Wo = (const float*)d_in[7];
    const float* bo = (const float*)d_in[8];
    float* out = (float*)d_out;

    __half *xh, *Wqkv, *Woh, *QK, *Vt, *P, *O;
    float *bqkv, *Sums;
    cudaGetSymbolAddress((void**)&xh, g_xh);
    cudaGetSymbolAddress((void**)&Wqkv, g_Wqkv);
    cudaGetSymbolAddress((void**)&bqkv, g_bqkv);
    cudaGetSymbolAddress((void**)&Woh, g_Wo);
    cudaGetSymbolAddress((void**)&QK, g_QK);
    cudaGetSymbolAddress((void**)&Vt, g_Vt);
    cudaGetSymbolAddress((void**)&P, g_P);
    cudaGetSymbolAddress((void**)&Sums, g_Sums);
    cudaGetSymbolAddress((void**)&O, g_O);

    const int S1 = 4 * 20480;      // 4-stage, 80 KB/CTA (2 CTAs/SM)
    cudaFuncSetAttribute(gemm<3>, cudaFuncAttributeMaxDynamicSharedMemorySize, S1);
    cudaFuncSetAttribute(gemm<1>, cudaFuncAttributeMaxDynamicSharedMemorySize, S1);
    cudaFuncSetAttribute(gemm<2>, cudaFuncAttributeMaxDynamicSharedMemorySize, S1);
    cudaFuncSetAttribute(gemm<0>, cudaFuncAttributeMaxDynamicSharedMemorySize, S1);

    const long SD  = (long)S_TOK * D_DIM;
    const long SS  = (long)S_TOK * S_TOK;
    const long SC  = (long)S_TOK * C_DIM;
    const long SQ  = (long)S_TOK * NQK;
    const long CS  = (long)C_DIM * S_TOK;
    const float attn_scale = 0.044194173824159216f;   // 512^-0.5

    // ---- prep ----
    transpose_x<<<dim3(S_TOK / 32, C_DIM / 32, BATCH), 256>>>(x, xh);
    prep_w<<<(D_DIM * C_DIM + 255) / 256, 256>>>(Wq, Wk, Wv, Wo, bq, bk, bv,
                                                 Wqkv, Woh, bqkv, Sums);

    // ---- fused QKV projection (N = 1536; Q scaled; V transposed) ----
    gemm<3><<<dim3(32, 12, BATCH), 256, S1>>>(
        xh, C_DIM, SC, C_DIM, Wqkv, C_DIM, 0,
        nullptr, QK, Vt, SQ, SD, NQK, bqkv, nullptr, attn_scale);

    // ---- P = exp(Q K^T) (fp32 acc); row sums -> Sums ----
    gemm<1><<<dim3(32, 32, BATCH), 256, S1>>>(
        QK, NQK, SQ, D_DIM, QK + 512, NQK, SQ,
        Sums, P, nullptr, SS, 0, S_TOK, nullptr, nullptr, 1.f);

    // ---- O = (P V) / rowsum ----
    gemm<2><<<dim3(32, 4, BATCH), 256, S1>>>(
        P, S_TOK, SS, S_TOK, Vt, S_TOK, SD,
        nullptr, O, nullptr, SD, 0, D_DIM, nullptr, Sums, 1.f);

    // ---- y = O Wo^T + bo (fp32 transposed store) ----
    gemm<0><<<dim3(32, 4, BATCH), 256, S1>>>(
        O, D_DIM, SD, D_DIM, Woh, D_DIM, 0,
        out, nullptr, nullptr, CS, 0, S_TOK, bo, nullptr, 1.f);
}